// round 15
// baseline (speedup 1.0000x reference)
#include <cuda_runtime.h>
#include <cuda_bf16.h>
#include <math.h>
#include <stdint.h>

#define NN 10
#define CC 512
#define HW 1600
#define OC 128
#define IMG 40
#define MROWS 1280
#define K1 4608
#define K2 1152
#define LDT 40

// ---------------- scratch ----------------
__device__ float g_NF[NN*CC*HW];
__device__ float g_SIVraw[NN*CC];
__device__ float g_SIV[NN*CC];
__device__ float g_cm[NN*NN*HW];
__device__ float g_corr[NN*NN*NN];
__device__ float g_sv[NN*NN];
__device__ float g_wv[NN*NN];
__device__ float g_CSA[NN*HW];
__device__ int   g_idx[NN*HW];
__device__ __align__(16) __nv_bfloat16 g_Wc_hi[MROWS*HW];
__device__ __align__(16) __nv_bfloat16 g_Wc_lo[MROWS*HW];
__device__ __align__(16) __nv_bfloat16 g_Ag_hi[NN*CC*HW];
__device__ __align__(16) __nv_bfloat16 g_Ag_lo[NN*CC*HW];
__device__ __align__(16) __nv_bfloat16 g_Wk1_hi[NN*OC*K1];
__device__ __align__(16) __nv_bfloat16 g_Wk1_lo[NN*OC*K1];
__device__ __align__(16) __nv_bfloat16 g_Wsc_hi[NN*OC*CC];
__device__ __align__(16) __nv_bfloat16 g_Wsc_lo[NN*OC*CC];
__device__ __align__(16) __nv_bfloat16 g_W2k_hi[OC*K2];
__device__ __align__(16) __nv_bfloat16 g_W2k_lo[OC*K2];
__device__ __align__(16) __nv_bfloat16 g_Xt_hi[NN*HW*CC];
__device__ __align__(16) __nv_bfloat16 g_Xt_lo[NN*HW*CC];
__device__ __align__(16) __nv_bfloat16 g_H1t_hi[NN*HW*OC];
__device__ __align__(16) __nv_bfloat16 g_H1t_lo[NN*HW*OC];
__device__ float g_SC[NN*OC*HW];

// ---------------- helpers ----------------
__device__ __forceinline__ double blockReduceSumD(double v) {
    __shared__ double sh[32];
    int lane = threadIdx.x & 31, wid = threadIdx.x >> 5;
#pragma unroll
    for (int o = 16; o > 0; o >>= 1) v += __shfl_down_sync(0xffffffffu, v, o);
    if (lane == 0) sh[wid] = v;
    __syncthreads();
    if (wid == 0) {
        int nw = blockDim.x >> 5;
        v = (lane < nw) ? sh[lane] : 0.0;
#pragma unroll
        for (int o = 16; o > 0; o >>= 1) v += __shfl_down_sync(0xffffffffu, v, o);
    }
    return v;
}
__device__ __forceinline__ void kadd(float& s, float& c, float p) {
    float y = __fsub_rn(p, c);
    float t = __fadd_rn(s, y);
    c = __fsub_rn(__fsub_rn(t, s), y);
    s = t;
}
__device__ __forceinline__ uint32_t smem_u32(const void* p) {
    uint32_t a;
    asm("{ .reg .u64 t; cvta.to.shared.u64 t, %1; cvt.u32.u64 %0, t; }" : "=r"(a) : "l"(p));
    return a;
}
__device__ __forceinline__ void ldsm_x4(uint32_t& r0, uint32_t& r1, uint32_t& r2, uint32_t& r3, uint32_t a) {
    asm volatile("ldmatrix.sync.aligned.m8n8.x4.shared.b16 {%0,%1,%2,%3}, [%4];"
                 : "=r"(r0), "=r"(r1), "=r"(r2), "=r"(r3) : "r"(a));
}
__device__ __forceinline__ void hmma(float* c, const uint32_t* a, uint32_t b0, uint32_t b1) {
    asm volatile("mma.sync.aligned.m16n8k16.row.col.f32.bf16.bf16.f32 "
                 "{%0,%1,%2,%3},{%4,%5,%6,%7},{%8,%9},{%0,%1,%2,%3};"
                 : "+f"(c[0]), "+f"(c[1]), "+f"(c[2]), "+f"(c[3])
                 : "r"(a[0]), "r"(a[1]), "r"(a[2]), "r"(a[3]), "r"(b0), "r"(b1));
}
__device__ __forceinline__ uint32_t pack_hi2(float a, float b) {
    __nv_bfloat16 ha = __float2bfloat16(a), hb = __float2bfloat16(b);
    return (uint32_t)__bfloat16_as_ushort(ha) | ((uint32_t)__bfloat16_as_ushort(hb) << 16);
}
__device__ __forceinline__ uint32_t pack_lo2(float a, float b) {
    __nv_bfloat16 ha = __float2bfloat16(a), hb = __float2bfloat16(b);
    __nv_bfloat16 la = __float2bfloat16(a - __bfloat162float(ha));
    __nv_bfloat16 lb = __float2bfloat16(b - __bfloat162float(hb));
    return (uint32_t)__bfloat16_as_ushort(la) | ((uint32_t)__bfloat16_as_ushort(lb) << 16);
}
// cp.async primitives (sm_80 baseline)
#define CPA16(sm, gp)       asm volatile("cp.async.cg.shared.global [%0], [%1], 16;" :: "r"(sm), "l"(gp))
#define CPA16P(sm, gp, ok)  asm volatile("cp.async.cg.shared.global [%0], [%1], 16, %2;" :: "r"(sm), "l"(gp), "r"((ok) ? 16 : 0))
#define CP_COMMIT()         asm volatile("cp.async.commit_group;")
#define CP_WAIT1()          asm volatile("cp.async.wait_group 1;")
#define CP_WAIT0()          asm volatile("cp.async.wait_group 0;")

// ---------------- 1: per-pixel L2 norm ----------------
__global__ void k_norm(const float* __restrict__ feats) {
    int n = blockIdx.y;
    int tid = threadIdx.x;
    int cg = tid >> 5, kk = tid & 31;
    int hw = blockIdx.x * 32 + kk;
    const float* f = feats + (size_t)n * CC * HW + hw;
    float s = 0.f, comp = 0.f;
    for (int c = cg * 64; c < cg * 64 + 64; c++) {
        float v = f[(size_t)c * HW];
        kadd(s, comp, __fmul_rn(v, v));
    }
    __shared__ double sh[8][32];
    __shared__ float sd[32];
    sh[cg][kk] = (double)s + (double)comp;
    __syncthreads();
    if (tid < 32) {
        double S = 0.0;
#pragma unroll
        for (int g = 0; g < 8; g++) S += sh[g][tid];
        sd[tid] = fmaxf(sqrtf((float)S), 1e-12f);
    }
    __syncthreads();
    float d = sd[kk];
    float* o = g_NF + (size_t)n * CC * HW + hw;
    for (int c = cg * 64; c < cg * 64 + 64; c++)
        o[(size_t)c * HW] = f[(size_t)c * HW] / d;
}

// ---------------- 2: SIV raw ----------------
__global__ void k_siv_raw(const float* __restrict__ sisms) {
    int b = blockIdx.x;
    int n = b >> 9;
    double s = 0.0;
    for (int k = threadIdx.x; k < HW; k += 256) {
        float pm = g_NF[(size_t)b * HW + k] * sisms[n * HW + k];
        s += (double)pm;
    }
    s = blockReduceSumD(s);
    if (threadIdx.x == 0) g_SIVraw[b] = ((float)s) / 1600.0f;
}

// ---------------- 3: SIV l2 norm ----------------
__global__ void k_siv_norm() {
    int n = blockIdx.x, t = threadIdx.x;
    float v = g_SIVraw[n * CC + t];
    float sq = v * v;
    double s = blockReduceSumD((double)sq);
    __shared__ float s_d;
    if (t == 0) s_d = fmaxf(sqrtf((float)s), 1e-12f);
    __syncthreads();
    g_SIV[n * CC + t] = v / s_d;
}

// ---------------- 4: cm ----------------
__global__ void k_cm() {
    __shared__ float s_siv[NN * CC];
    __shared__ double sh[8][32][NN];
    int n = blockIdx.y;
    int tid = threadIdx.x;
    for (int q = tid; q < NN * CC; q += 256) s_siv[q] = g_SIV[q];
    int cg = tid >> 5, kk = tid & 31;
    int k = blockIdx.x * 32 + kk;
    const float* nfp = g_NF + (size_t)n * CC * HW + k;
    __syncthreads();
    float s[NN], comp[NN];
#pragma unroll
    for (int m = 0; m < NN; m++) { s[m] = 0.f; comp[m] = 0.f; }
    for (int c = cg * 64; c < cg * 64 + 64; c++) {
        float nf = nfp[(size_t)c * HW];
#pragma unroll
        for (int m = 0; m < NN; m++) kadd(s[m], comp[m], __fmul_rn(nf, s_siv[m * CC + c]));
    }
#pragma unroll
    for (int m = 0; m < NN; m++) sh[cg][kk][m] = (double)s[m] + (double)comp[m];
    __syncthreads();
    for (int e = tid; e < 32 * NN; e += 256) {
        int kk2 = e / NN, m = e % NN;
        double v = 0.0;
#pragma unroll
        for (int g = 0; g < 8; g++) v += sh[g][kk2][m];
        g_cm[(size_t)(n * NN + m) * HW + blockIdx.x * 32 + kk2] = (float)v;
    }
}

// ---------------- 5: cm row norm ----------------
__global__ void k_cm_norm() {
    int row = blockIdx.x;
    size_t base = (size_t)row * HW;
    double ss = 0.0;
    for (int k = threadIdx.x; k < HW; k += 256) {
        float v = g_cm[base + k];
        float sq = v * v;
        ss += (double)sq;
    }
    ss = blockReduceSumD(ss);
    __shared__ float s_d;
    if (threadIdx.x == 0) s_d = fmaxf(sqrtf((float)ss), 1e-12f);
    __syncthreads();
    for (int k = threadIdx.x; k < HW; k += 256) g_cm[base + k] = g_cm[base + k] / s_d;
}

// ---------------- 6: corr ----------------
__global__ void k_corr() {
    int b = blockIdx.x;
    int p = b % NN;
    int m = (b / NN) % NN;
    int n = b / (NN * NN);
    double s = 0.0;
    for (int k = threadIdx.x; k < HW; k += 256)
        s += (double)g_cm[(size_t)(n * NN + m) * HW + k] * (double)g_cm[(size_t)(n * NN + p) * HW + k];
    s = blockReduceSumD(s);
    if (threadIdx.x == 0) g_corr[b] = (float)s;
}

// ---------------- 7: sv + softmax fused ----------------
__global__ void k_svsm() {
    int t = threadIdx.x;
    if (t < NN * NN) {
        double s = 0.0;
#pragma unroll
        for (int p = 0; p < NN; p++) s += (double)g_corr[t * NN + p];
        g_sv[t] = (float)s;
    }
    __syncthreads();
    int n = t;
    if (n >= NN) return;
    float mx = -1e30f;
    for (int m = 0; m < NN; m++) mx = fmaxf(mx, g_sv[n * NN + m]);
    float e[NN];
    double sum = 0.0;
    for (int m = 0; m < NN; m++) {
        float tt = g_sv[n * NN + m] - mx;
        e[m] = (float)exp((double)tt);
        sum += (double)e[m];
    }
    float S = (float)sum;
    for (int m = 0; m < NN; m++) g_wv[n * NN + m] = e[m] / S;
}

// ---------------- 8: CSA + argsort fused ----------------
__global__ void k_csasort() {
    __shared__ float key[2048];
    __shared__ int   idv[2048];
    __shared__ float s_wv[NN];
    __shared__ float red[1024];
    int n = blockIdx.x, tid = threadIdx.x;
    if (tid < NN) s_wv[tid] = g_wv[n * NN + tid];
    __syncthreads();
    float lmin = 1e30f, lmax = -1e30f;
    for (int k = tid; k < HW; k += 1024) {
        double a = 0.0;
#pragma unroll
        for (int m = 0; m < NN; m++) {
            float pm = g_cm[(size_t)(n * NN + m) * HW + k] * s_wv[m];
            a += (double)pm;
        }
        float raw = (float)a;
        key[k] = raw;
        lmin = fminf(lmin, raw); lmax = fmaxf(lmax, raw);
    }
    red[tid] = lmin; __syncthreads();
    for (int s = 512; s > 0; s >>= 1) { if (tid < s) red[tid] = fminf(red[tid], red[tid + s]); __syncthreads(); }
    float mn = red[0]; __syncthreads();
    red[tid] = lmax; __syncthreads();
    for (int s = 512; s > 0; s >>= 1) { if (tid < s) red[tid] = fmaxf(red[tid], red[tid + s]); __syncthreads(); }
    float mx = red[0]; __syncthreads();
    float den = (mx - mn) + 1e-12f;
    for (int k = tid; k < HW; k += 1024) {
        float v = (key[k] - mn) / den;
        key[k] = v;
        g_CSA[n * HW + k] = v;
        idv[k] = k;
    }
    for (int e = HW + tid; e < 2048; e += 1024) { key[e] = -1e30f; idv[e] = e; }
    __syncthreads();
    for (int k = 2; k <= 2048; k <<= 1) {
        for (int j = k >> 1; j > 0; j >>= 1) {
            for (int e = tid; e < 2048; e += 1024) {
                int ix = e ^ j;
                if (ix > e) {
                    float ka = key[e], kb = key[ix];
                    int ia = idv[e], ib = idv[ix];
                    bool up = ((e & k) == 0);
                    bool b_before_a = (kb > ka) || (kb == ka && ib < ia);
                    bool dosw = up ? b_before_a : !b_before_a;
                    if (dosw) { key[e] = kb; key[ix] = ka; idv[e] = ib; idv[ix] = ia; }
                }
            }
            __syncthreads();
        }
    }
    for (int e = tid; e < HW; e += 1024) g_idx[n * HW + e] = idv[e];
}

// ---------------- 9: gather + bf16 split ----------------
__global__ void k_gather_split() {
    int b = blockIdx.x;
    int n = b >> 9;
    for (int i = threadIdx.x; i < HW; i += 256) {
        float v = g_NF[(size_t)b * HW + g_idx[n * HW + i]];
        __nv_bfloat16 h = __float2bfloat16(v);
        __nv_bfloat16 l = __float2bfloat16(v - __bfloat162float(h));
        g_Ag_hi[(size_t)b * HW + i] = h;
        g_Ag_lo[(size_t)b * HW + i] = l;
    }
}

// ---------------- 10: weight concat + split ----------------
__global__ void k_wsplit(const float* __restrict__ w1, const float* __restrict__ ws) {
    int q = blockIdx.x * 256 + threadIdx.x;
    if (q >= MROWS * HW) return;
    int i = q % HW, r = q / HW;
    float f;
    if (r < OC * 9) {
        int o = r / 9, t = r % 9;
        f = w1[(o * HW + i) * 9 + t];
    } else {
        f = ws[(r - OC * 9) * HW + i];
    }
    __nv_bfloat16 h = __float2bfloat16(f);
    __nv_bfloat16 l = __float2bfloat16(f - __bfloat162float(h));
    g_Wc_hi[q] = h;
    g_Wc_lo[q] = l;
}
__global__ void k_w2split(const float* __restrict__ w2) {
    int q = blockIdx.x * 256 + threadIdx.x;
    if (q >= OC * K2) return;
    int k = q % K2, o = q / K2;
    int t = k / OC, c = k % OC;
    float f = w2[(o * OC + c) * 9 + t];
    __nv_bfloat16 h = __float2bfloat16(f);
    __nv_bfloat16 l = __float2bfloat16(f - __bfloat162float(h));
    g_W2k_hi[q] = h;
    g_W2k_lo[q] = l;
}

// ---------------- 11: fold GEMM, cp.async double-buffered, 2 CTAs/SM -------------
#define FBUF 10240
#define FSTAGE (4 * FBUF)

__global__ __launch_bounds__(256, 2) void k_gemm_mma() {
    extern __shared__ __align__(16) char dsm[];
    uint32_t base = smem_u32(dsm);
    int n = blockIdx.z;
    int m0 = blockIdx.x * 128, n0 = blockIdx.y * 128;
    const __nv_bfloat16* Bh = g_Ag_hi + (size_t)n * CC * HW;
    const __nv_bfloat16* Bl = g_Ag_lo + (size_t)n * CC * HW;
    int tid = threadIdx.x, lane = tid & 31, wid = tid >> 5;
    int wm = wid & 3, wn = wid >> 2;

    float c[2][8][4];
#pragma unroll
    for (int i = 0; i < 2; i++)
#pragma unroll
        for (int j = 0; j < 8; j++)
#pragma unroll
            for (int q = 0; q < 4; q++) c[i][j][q] = 0.f;

    int lrow = tid >> 1, lk = (tid & 1) * 16;
    const __nv_bfloat16* pAh = g_Wc_hi + (size_t)(m0 + lrow) * HW + lk;
    const __nv_bfloat16* pAl = g_Wc_lo + (size_t)(m0 + lrow) * HW + lk;
    const __nv_bfloat16* pBh = Bh + (size_t)(n0 + lrow) * HW + lk;
    const __nv_bfloat16* pBl = Bl + (size_t)(n0 + lrow) * HW + lk;
    uint32_t so = (uint32_t)(lrow * LDT + lk) * 2;
    int arow = (lane & 15), akoff = 8 * (lane >> 4);
    int bcol = 8 * ((lane >> 4) & 1) + (lane & 7);
    int bko  = 8 * ((lane >> 3) & 1);

#define FCP(s, k0) do { \
    uint32_t sb = base + (s) * FSTAGE + so; \
    CPA16(sb,               pAh + (k0)); CPA16(sb + 16,               pAh + (k0) + 8); \
    CPA16(sb + FBUF,        pAl + (k0)); CPA16(sb + FBUF + 16,        pAl + (k0) + 8); \
    CPA16(sb + 2*FBUF,      pBh + (k0)); CPA16(sb + 2*FBUF + 16,      pBh + (k0) + 8); \
    CPA16(sb + 3*FBUF,      pBl + (k0)); CPA16(sb + 3*FBUF + 16,      pBl + (k0) + 8); \
    CP_COMMIT(); } while (0)

    FCP(0, 0);
    for (int kb = 0; kb < 50; kb++) {
        bool more = (kb + 1 < 50);
        if (more) { FCP((kb + 1) & 1, (kb + 1) * 32); CP_WAIT1(); }
        else      { CP_WAIT0(); }
        __syncthreads();
        uint32_t uAh = base + (kb & 1) * FSTAGE;
        uint32_t uAl = uAh + FBUF, uBh = uAh + 2 * FBUF, uBl = uAh + 3 * FBUF;
#pragma unroll
        for (int kk = 0; kk < 32; kk += 16) {
            uint32_t ah[2][4], al[2][4];
#pragma unroll
            for (int i = 0; i < 2; i++) {
                uint32_t ao = (uint32_t)((32 * wm + 16 * i + arow) * LDT + kk + akoff) * 2;
                ldsm_x4(ah[i][0], ah[i][1], ah[i][2], ah[i][3], uAh + ao);
                ldsm_x4(al[i][0], al[i][1], al[i][2], al[i][3], uAl + ao);
            }
#pragma unroll
            for (int jp = 0; jp < 8; jp += 2) {
                uint32_t bo = (uint32_t)((64 * wn + 8 * jp + bcol) * LDT + kk + bko) * 2;
                uint32_t bh0, bh1, bh2, bh3, bl0, bl1, bl2, bl3;
                ldsm_x4(bh0, bh1, bh2, bh3, uBh + bo);
                ldsm_x4(bl0, bl1, bl2, bl3, uBl + bo);
#pragma unroll
                for (int i = 0; i < 2; i++) {
                    hmma(c[i][jp], ah[i], bh0, bh1);
                    hmma(c[i][jp], ah[i], bl0, bl1);
                    hmma(c[i][jp], al[i], bh0, bh1);
                    hmma(c[i][jp + 1], ah[i], bh2, bh3);
                    hmma(c[i][jp + 1], ah[i], bl2, bl3);
                    hmma(c[i][jp + 1], al[i], bh2, bh3);
                }
            }
        }
        __syncthreads();
    }
#undef FCP
#pragma unroll
    for (int i = 0; i < 2; i++) {
        int rb = m0 + 32 * wm + 16 * i + (lane >> 2);
#pragma unroll
        for (int half = 0; half < 2; half++) {
            int r = rb + half * 8;
#pragma unroll
            for (int j = 0; j < 8; j++) {
                int col = n0 + 64 * wn + 8 * j + (lane & 3) * 2;
                float v0 = c[i][j][half * 2], v1 = c[i][j][half * 2 + 1];
                size_t off;
                __nv_bfloat16 *dh, *dl;
                if (r < OC * 9) {
                    int o = r / 9, t = r % 9;
                    off = ((size_t)n * OC + o) * K1 + t * CC + col;
                    dh = g_Wk1_hi; dl = g_Wk1_lo;
                } else {
                    int o = r - OC * 9;
                    off = ((size_t)n * OC + o) * CC + col;
                    dh = g_Wsc_hi; dl = g_Wsc_lo;
                }
                *(uint32_t*)(dh + off) = pack_hi2(v0, v1);
                *(uint32_t*)(dl + off) = pack_lo2(v0, v1);
            }
        }
    }
}

// ---------------- 12: Xt = (NF*CSA)^T split ----------------
__global__ void k_xt() {
    __shared__ float sT[32][33];
    int n = blockIdx.z;
    int p0 = blockIdx.x * 32, c0 = blockIdx.y * 32;
    int tid = threadIdx.x;
    int tc = tid >> 5, tp = tid & 31;
#pragma unroll
    for (int r = 0; r < 4; r++) {
        int c = c0 + tc + r * 8;
        sT[tc + r * 8][tp] = g_NF[((size_t)n * CC + c) * HW + p0 + tp] * g_CSA[n * HW + p0 + tp];
    }
    __syncthreads();
#pragma unroll
    for (int r = 0; r < 4; r++) {
        int p = p0 + tc + r * 8;
        float v = sT[tp][tc + r * 8];
        __nv_bfloat16 h = __float2bfloat16(v);
        __nv_bfloat16 l = __float2bfloat16(v - __bfloat162float(h));
        g_Xt_hi[((size_t)n * HW + p) * CC + c0 + tp] = h;
        g_Xt_lo[((size_t)n * HW + p) * CC + c0 + tp] = l;
    }
}

// ---------------- 13: conv, cp.async double-buffered, 2 CTAs/SM ----------
#define CBUF 10240
#define CSTG (4 * CBUF)

__global__ __launch_bounds__(256, 2) void k_conv_mma(int mode, const float* __restrict__ bias,
                                                     const float* __restrict__ bsc,
                                                     float* __restrict__ dout) {
    extern __shared__ __align__(16) char dsm[];
    uint32_t base = smem_u32(dsm);
    int n = blockIdx.z;
    int p0 = blockIdx.x * 128;
    int tid = threadIdx.x, lane = tid & 31, wid = tid >> 5;
    int wm = wid & 3, wn = wid >> 2;

    const __nv_bfloat16 *Ah, *Al, *Bh, *Bl;
    int K, Cin, nslab;
    if (mode == 0) {
        Ah = g_Wk1_hi + (size_t)n * OC * K1; Al = g_Wk1_lo + (size_t)n * OC * K1;
        Bh = g_Xt_hi + (size_t)n * HW * CC;  Bl = g_Xt_lo + (size_t)n * HW * CC;
        K = K1; Cin = CC; nslab = K1 / 32;
    } else {
        Ah = g_W2k_hi; Al = g_W2k_lo;
        Bh = g_H1t_hi + (size_t)n * HW * OC; Bl = g_H1t_lo + (size_t)n * HW * OC;
        K = K2; Cin = OC; nslab = K2 / 32;
    }
    int slabs_per_tap = Cin / 32;

    int lrow = tid >> 1, lk = (tid & 1) * 16;
    int bp = p0 + lrow;
    bool prow = (bp < HW);
    int bpx = bp % IMG, bpy = bp / IMG;
    int arow = (lane & 15), akoff = 8 * (lane >> 4);
    int bcol = 8 * ((lane >> 4) & 1) + (lane & 7);
    int bko  = 8 * ((lane >> 3) & 1);
    uint32_t so = (uint32_t)(lrow * LDT + lk) * 2;

    float c[2][8][4];
#pragma unroll
    for (int i = 0; i < 2; i++)
#pragma unroll
        for (int j = 0; j < 8; j++)
#pragma unroll
            for (int q = 0; q < 4; q++) c[i][j][q] = 0.f;

#define CCP(s, kb) do { \
    int t_ = (kb) / slabs_per_tap, c0_ = ((kb) % slabs_per_tap) * 32; \
    int dy_ = t_ / 3 - 1, dx_ = t_ % 3 - 1, off_ = dy_ * IMG + dx_; \
    bool valid_ = prow && ((unsigned)(bpx + dx_) < (unsigned)IMG) && ((unsigned)(bpy + dy_) < (unsigned)IMG); \
    size_t gA_ = (size_t)lrow * K + (kb) * 32 + lk; \
    size_t gB_ = (size_t)(bp + off_) * Cin + c0_ + lk; \
    const __nv_bfloat16* gb_ = valid_ ? (Bh + gB_) : Bh; \
    const __nv_bfloat16* gb2_ = valid_ ? (Bl + gB_) : Bl; \
    uint32_t sb = base + (s) * CSTG + so; \
    CPA16(sb,            Ah + gA_); CPA16(sb + 16,            Ah + gA_ + 8); \
    CPA16(sb + CBUF,     Al + gA_); CPA16(sb + CBUF + 16,     Al + gA_ + 8); \
    CPA16P(sb + 2*CBUF,  gb_, valid_); CPA16P(sb + 2*CBUF + 16, gb_ + 8, valid_); \
    CPA16P(sb + 3*CBUF,  gb2_, valid_); CPA16P(sb + 3*CBUF + 16, gb2_ + 8, valid_); \
    CP_COMMIT(); } while (0)
#define CCOMPUTE(s) do { \
    uint32_t uAh_ = base + (s) * CSTG; \
    uint32_t uAl_ = uAh_ + CBUF, uBh_ = uAh_ + 2*CBUF, uBl_ = uAh_ + 3*CBUF; \
    _Pragma("unroll") \
    for (int kk = 0; kk < 32; kk += 16) { \
        uint32_t ah[2][4], al[2][4]; \
        _Pragma("unroll") \
        for (int i = 0; i < 2; i++) { \
            uint32_t ao = (uint32_t)((32 * wm + 16 * i + arow) * LDT + kk + akoff) * 2; \
            ldsm_x4(ah[i][0], ah[i][1], ah[i][2], ah[i][3], uAh_ + ao); \
            ldsm_x4(al[i][0], al[i][1], al[i][2], al[i][3], uAl_ + ao); \
        } \
        _Pragma("unroll") \
        for (int jp = 0; jp < 8; jp += 2) { \
            uint32_t bo = (uint32_t)((64 * wn + 8 * jp + bcol) * LDT + kk + bko) * 2; \
            uint32_t bh0, bh1, bh2, bh3, bl0, bl1, bl2, bl3; \
            ldsm_x4(bh0, bh1, bh2, bh3, uBh_ + bo); \
            ldsm_x4(bl0, bl1, bl2, bl3, uBl_ + bo); \
            _Pragma("unroll") \
            for (int i = 0; i < 2; i++) { \
                hmma(c[i][jp], ah[i], bh0, bh1); \
                hmma(c[i][jp], ah[i], bl0, bl1); \
                hmma(c[i][jp], al[i], bh0, bh1); \
                hmma(c[i][jp + 1], ah[i], bh2, bh3); \
                hmma(c[i][jp + 1], ah[i], bl2, bl3); \
                hmma(c[i][jp + 1], al[i], bh2, bh3); \
            } \
        } \
    } } while (0)

    CCP(0, 0);
    for (int kb = 0; kb < nslab; kb++) {
        bool more = (kb + 1 < nslab);
        if (more) { CCP((kb + 1) & 1, kb + 1); CP_WAIT1(); }
        else      { CP_WAIT0(); }
        __syncthreads();
        CCOMPUTE(kb & 1);
        __syncthreads();
    }
    // epilogue phase 1
#pragma unroll
    for (int i = 0; i < 2; i++) {
        int rb = 32 * wm + 16 * i + (lane >> 2);
#pragma unroll
        for (int half = 0; half < 2; half++) {
            int o = rb + half * 8;
            float bo = bias[o];
#pragma unroll
            for (int j = 0; j < 8; j++) {
                int p = p0 + 64 * wn + 8 * j + (lane & 3) * 2;
                if (p >= HW) continue;
                float v0 = c[i][j][half * 2] + bo, v1 = c[i][j][half * 2 + 1] + bo;
                if (mode == 0) {
                    float a = fmaxf(v0, 0.f), b2 = fmaxf(v1, 0.f);
                    __nv_bfloat16 ha = __float2bfloat16(a);
                    __nv_bfloat16 la = __float2bfloat16(a - __bfloat162float(ha));
                    __nv_bfloat16 hb = __float2bfloat16(b2);
                    __nv_bfloat16 lb = __float2bfloat16(b2 - __bfloat162float(hb));
                    size_t b0 = ((size_t)n * HW + p) * OC + o;
                    g_H1t_hi[b0] = ha; g_H1t_lo[b0] = la;
                    g_H1t_hi[b0 + OC] = hb; g_H1t_lo[b0 + OC] = lb;
                } else {
                    float2 sc = *(const float2*)&g_SC[((size_t)n * OC + o) * HW + p];
                    *(float2*)&dout[((size_t)n * OC + o) * HW + p] =
                        make_float2(fmaxf(v0 + sc.x, 0.f), fmaxf(v1 + sc.y, 0.f));
                }
            }
        }
    }
    if (mode != 0) return;

    // ---- phase 2: 1x1 shortcut (K=512) ----
#pragma unroll
    for (int i = 0; i < 2; i++)
#pragma unroll
        for (int j = 0; j < 8; j++)
#pragma unroll
            for (int q = 0; q < 4; q++) c[i][j][q] = 0.f;
    const __nv_bfloat16* Sh = g_Wsc_hi + (size_t)n * OC * CC;
    const __nv_bfloat16* Sl = g_Wsc_lo + (size_t)n * OC * CC;
#define SCP(s, kb) do { \
    size_t gA_ = (size_t)lrow * CC + (kb) * 32 + lk; \
    size_t gB_ = (size_t)bp * CC + (kb) * 32 + lk; \
    const __nv_bfloat16* gb_ = prow ? (Bh + gB_) : Bh; \
    const __nv_bfloat16* gb2_ = prow ? (Bl + gB_) : Bl; \
    uint32_t sb = base + (s) * CSTG + so; \
    CPA16(sb,            Sh + gA_); CPA16(sb + 16,            Sh + gA_ + 8); \
    CPA16(sb + CBUF,     Sl + gA_); CPA16(sb + CBUF + 16,     Sl + gA_ + 8); \
    CPA16P(sb + 2*CBUF,  gb_, prow); CPA16P(sb + 2*CBUF + 16, gb_ + 8, prow); \
    CPA16P(sb + 3*CBUF,  gb2_, prow); CPA16P(sb + 3*CBUF + 16, gb2_ + 8, prow); \
    CP_COMMIT(); } while (0)

    __syncthreads();
    SCP(0, 0);
    for (int kb = 0; kb < CC / 32; kb++) {
        bool more = (kb + 1 < CC / 32);
        if (more) { SCP((kb + 1) & 1, kb + 1); CP_WAIT1(); }
        else      { CP_WAIT0(); }
        __syncthreads();
        CCOMPUTE(kb & 1);
        __syncthreads();
    }
#undef SCP
#undef CCP
#undef CCOMPUTE
#pragma unroll
    for (int i = 0; i < 2; i++) {
        int rb = 32 * wm + 16 * i + (lane >> 2);
#pragma unroll
        for (int half = 0; half < 2; half++) {
            int o = rb + half * 8;
            float bo = bsc[o];
#pragma unroll
            for (int j = 0; j < 8; j++) {
                int p = p0 + 64 * wn + 8 * j + (lane & 3) * 2;
                if (p >= HW) continue;
                *(float2*)&g_SC[((size_t)n * OC + o) * HW + p] =
                    make_float2(c[i][j][half * 2] + bo, c[i][j][half * 2 + 1] + bo);
            }
        }
    }
}

// ---------------- launch ----------------
extern "C" void kernel_launch(void* const* d_in, const int* in_sizes, int n_in,
                              void* d_out, int out_size) {
    const float *feats = nullptr, *sisms = nullptr, *w1 = nullptr, *w2 = nullptr, *ws = nullptr;
    const float *b1 = nullptr, *b2 = nullptr, *bs = nullptr;
    for (int i = 0; i < n_in; i++) {
        int s = in_sizes[i];
        const float* p = (const float*)d_in[i];
        if (s == NN * CC * HW) feats = p;
        else if (s == NN * HW) sisms = p;
        else if (s == OC * HW * 9) w1 = p;
        else if (s == OC * OC * 9) w2 = p;
        else if (s == OC * HW) ws = p;
        else if (s == OC) { if (!b1) b1 = p; else if (!b2) b2 = p; else bs = p; }
    }
    float* out = (float*)d_out;

    static int attr_set = 0;
    if (!attr_set) {
        cudaFuncSetAttribute(k_gemm_mma, cudaFuncAttributeMaxDynamicSharedMemorySize, 2 * FSTAGE);
        cudaFuncSetAttribute(k_conv_mma, cudaFuncAttributeMaxDynamicSharedMemorySize, 2 * CSTG);
        attr_set = 1;
    }

    k_norm<<<dim3(50, NN), 256>>>(feats);
    k_siv_raw<<<NN * CC, 256>>>(sisms);
    k_siv_norm<<<NN, CC>>>();
    k_cm<<<dim3(50, NN), 256>>>();
    k_cm_norm<<<NN * NN, 256>>>();
    k_corr<<<NN * NN * NN, 256>>>();
    k_svsm<<<1, 128>>>();
    k_csasort<<<NN, 1024>>>();
    k_gather_split<<<NN * CC, 256>>>();
    k_wsplit<<<(MROWS * HW + 255) / 256, 256>>>(w1, ws);
    k_w2split<<<(OC * K2 + 255) / 256, 256>>>(w2);
    k_gemm_mma<<<dim3(MROWS / 128, CC / 128, NN), 256, 2 * FSTAGE>>>();
    k_xt<<<dim3(50, CC / 32, NN), 256>>>();
    k_conv_mma<<<dim3(13, 1, NN), 256, 2 * CSTG>>>(0, b1, bs, nullptr);
    k_conv_mma<<<dim3(13, 1, NN), 256, 2 * CSTG>>>(1, b2, nullptr, out);
    (void)out_size; (void)n_in;
}

// round 16
// speedup vs baseline: 1.0709x; 1.0709x over previous
#include <cuda_runtime.h>
#include <cuda_bf16.h>
#include <math.h>
#include <stdint.h>

#define NN 10
#define CC 512
#define HW 1600
#define OC 128
#define IMG 40
#define MROWS 1280
#define K1 4608
#define K2 1152
#define LDT 40

// ---------------- scratch ----------------
__device__ float g_NF[NN*CC*HW];
__device__ float g_SIVraw[NN*CC];
__device__ float g_SIV[NN*CC];
__device__ float g_cm[NN*NN*HW];
__device__ float g_corr[NN*NN*NN];
__device__ float g_sv[NN*NN];
__device__ float g_wv[NN*NN];
__device__ float g_CSA[NN*HW];
__device__ int   g_idx[NN*HW];
__device__ __align__(16) __nv_bfloat16 g_Wc_hi[MROWS*HW];
__device__ __align__(16) __nv_bfloat16 g_Wc_lo[MROWS*HW];
__device__ __align__(16) __nv_bfloat16 g_Ag_hi[NN*CC*HW];
__device__ __align__(16) __nv_bfloat16 g_Ag_lo[NN*CC*HW];
__device__ __align__(16) __nv_bfloat16 g_Wk1_hi[NN*OC*K1];
__device__ __align__(16) __nv_bfloat16 g_Wk1_lo[NN*OC*K1];
__device__ __align__(16) __nv_bfloat16 g_Wsc_hi[NN*OC*CC];
__device__ __align__(16) __nv_bfloat16 g_Wsc_lo[NN*OC*CC];
__device__ __align__(16) __nv_bfloat16 g_W2k_hi[OC*K2];
__device__ __align__(16) __nv_bfloat16 g_W2k_lo[OC*K2];
__device__ __align__(16) __nv_bfloat16 g_Xt_hi[NN*HW*CC];
__device__ __align__(16) __nv_bfloat16 g_Xt_lo[NN*HW*CC];
__device__ __align__(16) __nv_bfloat16 g_H1t_hi[NN*HW*OC];
__device__ __align__(16) __nv_bfloat16 g_H1t_lo[NN*HW*OC];
__device__ float g_SC[NN*OC*HW];

// ---------------- helpers ----------------
__device__ __forceinline__ double blockReduceSumD(double v) {
    __shared__ double sh[32];
    int lane = threadIdx.x & 31, wid = threadIdx.x >> 5;
#pragma unroll
    for (int o = 16; o > 0; o >>= 1) v += __shfl_down_sync(0xffffffffu, v, o);
    if (lane == 0) sh[wid] = v;
    __syncthreads();
    if (wid == 0) {
        int nw = blockDim.x >> 5;
        v = (lane < nw) ? sh[lane] : 0.0;
#pragma unroll
        for (int o = 16; o > 0; o >>= 1) v += __shfl_down_sync(0xffffffffu, v, o);
    }
    return v;
}
__device__ __forceinline__ void kadd(float& s, float& c, float p) {
    float y = __fsub_rn(p, c);
    float t = __fadd_rn(s, y);
    c = __fsub_rn(__fsub_rn(t, s), y);
    s = t;
}
__device__ __forceinline__ uint32_t smem_u32(const void* p) {
    uint32_t a;
    asm("{ .reg .u64 t; cvta.to.shared.u64 t, %1; cvt.u32.u64 %0, t; }" : "=r"(a) : "l"(p));
    return a;
}
__device__ __forceinline__ void ldsm_x4(uint32_t& r0, uint32_t& r1, uint32_t& r2, uint32_t& r3, uint32_t a) {
    asm volatile("ldmatrix.sync.aligned.m8n8.x4.shared.b16 {%0,%1,%2,%3}, [%4];"
                 : "=r"(r0), "=r"(r1), "=r"(r2), "=r"(r3) : "r"(a));
}
__device__ __forceinline__ void hmma(float* c, const uint32_t* a, uint32_t b0, uint32_t b1) {
    asm volatile("mma.sync.aligned.m16n8k16.row.col.f32.bf16.bf16.f32 "
                 "{%0,%1,%2,%3},{%4,%5,%6,%7},{%8,%9},{%0,%1,%2,%3};"
                 : "+f"(c[0]), "+f"(c[1]), "+f"(c[2]), "+f"(c[3])
                 : "r"(a[0]), "r"(a[1]), "r"(a[2]), "r"(a[3]), "r"(b0), "r"(b1));
}
__device__ __forceinline__ uint32_t pack_hi2(float a, float b) {
    __nv_bfloat16 ha = __float2bfloat16(a), hb = __float2bfloat16(b);
    return (uint32_t)__bfloat16_as_ushort(ha) | ((uint32_t)__bfloat16_as_ushort(hb) << 16);
}
__device__ __forceinline__ uint32_t pack_lo2(float a, float b) {
    __nv_bfloat16 ha = __float2bfloat16(a), hb = __float2bfloat16(b);
    __nv_bfloat16 la = __float2bfloat16(a - __bfloat162float(ha));
    __nv_bfloat16 lb = __float2bfloat16(b - __bfloat162float(hb));
    return (uint32_t)__bfloat16_as_ushort(la) | ((uint32_t)__bfloat16_as_ushort(lb) << 16);
}

// ---------------- 1: per-pixel L2 norm ----------------
__global__ void k_norm(const float* __restrict__ feats) {
    int n = blockIdx.y;
    int tid = threadIdx.x;
    int cg = tid >> 5, kk = tid & 31;
    int hw = blockIdx.x * 32 + kk;
    const float* f = feats + (size_t)n * CC * HW + hw;
    float s = 0.f, comp = 0.f;
    for (int c = cg * 64; c < cg * 64 + 64; c++) {
        float v = f[(size_t)c * HW];
        kadd(s, comp, __fmul_rn(v, v));
    }
    __shared__ double sh[8][32];
    __shared__ float sd[32];
    sh[cg][kk] = (double)s + (double)comp;
    __syncthreads();
    if (tid < 32) {
        double S = 0.0;
#pragma unroll
        for (int g = 0; g < 8; g++) S += sh[g][tid];
        sd[tid] = fmaxf(sqrtf((float)S), 1e-12f);
    }
    __syncthreads();
    float d = sd[kk];
    float* o = g_NF + (size_t)n * CC * HW + hw;
    for (int c = cg * 64; c < cg * 64 + 64; c++)
        o[(size_t)c * HW] = f[(size_t)c * HW] / d;
}

// ---------------- 2: SIV raw ----------------
__global__ void k_siv_raw(const float* __restrict__ sisms) {
    int b = blockIdx.x;
    int n = b >> 9;
    double s = 0.0;
    for (int k = threadIdx.x; k < HW; k += 256) {
        float pm = g_NF[(size_t)b * HW + k] * sisms[n * HW + k];
        s += (double)pm;
    }
    s = blockReduceSumD(s);
    if (threadIdx.x == 0) g_SIVraw[b] = ((float)s) / 1600.0f;
}

// ---------------- 3: SIV l2 norm ----------------
__global__ void k_siv_norm() {
    int n = blockIdx.x, t = threadIdx.x;
    float v = g_SIVraw[n * CC + t];
    float sq = v * v;
    double s = blockReduceSumD((double)sq);
    __shared__ float s_d;
    if (t == 0) s_d = fmaxf(sqrtf((float)s), 1e-12f);
    __syncthreads();
    g_SIV[n * CC + t] = v / s_d;
}

// ---------------- 4: cm ----------------
__global__ void k_cm() {
    __shared__ float s_siv[NN * CC];
    __shared__ double sh[8][32][NN];
    int n = blockIdx.y;
    int tid = threadIdx.x;
    for (int q = tid; q < NN * CC; q += 256) s_siv[q] = g_SIV[q];
    int cg = tid >> 5, kk = tid & 31;
    int k = blockIdx.x * 32 + kk;
    const float* nfp = g_NF + (size_t)n * CC * HW + k;
    __syncthreads();
    float s[NN], comp[NN];
#pragma unroll
    for (int m = 0; m < NN; m++) { s[m] = 0.f; comp[m] = 0.f; }
    for (int c = cg * 64; c < cg * 64 + 64; c++) {
        float nf = nfp[(size_t)c * HW];
#pragma unroll
        for (int m = 0; m < NN; m++) kadd(s[m], comp[m], __fmul_rn(nf, s_siv[m * CC + c]));
    }
#pragma unroll
    for (int m = 0; m < NN; m++) sh[cg][kk][m] = (double)s[m] + (double)comp[m];
    __syncthreads();
    for (int e = tid; e < 32 * NN; e += 256) {
        int kk2 = e / NN, m = e % NN;
        double v = 0.0;
#pragma unroll
        for (int g = 0; g < 8; g++) v += sh[g][kk2][m];
        g_cm[(size_t)(n * NN + m) * HW + blockIdx.x * 32 + kk2] = (float)v;
    }
}

// ---------------- 5: cm row norm ----------------
__global__ void k_cm_norm() {
    int row = blockIdx.x;
    size_t base = (size_t)row * HW;
    double ss = 0.0;
    for (int k = threadIdx.x; k < HW; k += 256) {
        float v = g_cm[base + k];
        float sq = v * v;
        ss += (double)sq;
    }
    ss = blockReduceSumD(ss);
    __shared__ float s_d;
    if (threadIdx.x == 0) s_d = fmaxf(sqrtf((float)ss), 1e-12f);
    __syncthreads();
    for (int k = threadIdx.x; k < HW; k += 256) g_cm[base + k] = g_cm[base + k] / s_d;
}

// ---------------- 6: corr ----------------
__global__ void k_corr() {
    int b = blockIdx.x;
    int p = b % NN;
    int m = (b / NN) % NN;
    int n = b / (NN * NN);
    double s = 0.0;
    for (int k = threadIdx.x; k < HW; k += 256)
        s += (double)g_cm[(size_t)(n * NN + m) * HW + k] * (double)g_cm[(size_t)(n * NN + p) * HW + k];
    s = blockReduceSumD(s);
    if (threadIdx.x == 0) g_corr[b] = (float)s;
}

// ---------------- 7: sv + softmax fused ----------------
__global__ void k_svsm() {
    int t = threadIdx.x;
    if (t < NN * NN) {
        double s = 0.0;
#pragma unroll
        for (int p = 0; p < NN; p++) s += (double)g_corr[t * NN + p];
        g_sv[t] = (float)s;
    }
    __syncthreads();
    int n = t;
    if (n >= NN) return;
    float mx = -1e30f;
    for (int m = 0; m < NN; m++) mx = fmaxf(mx, g_sv[n * NN + m]);
    float e[NN];
    double sum = 0.0;
    for (int m = 0; m < NN; m++) {
        float tt = g_sv[n * NN + m] - mx;
        e[m] = (float)exp((double)tt);
        sum += (double)e[m];
    }
    float S = (float)sum;
    for (int m = 0; m < NN; m++) g_wv[n * NN + m] = e[m] / S;
}

// ---------------- 8: CSA + argsort fused (1024 threads) ----------------
__global__ void k_csasort() {
    __shared__ float key[2048];
    __shared__ int   idv[2048];
    __shared__ float s_wv[NN];
    __shared__ float red[1024];
    int n = blockIdx.x, tid = threadIdx.x;
    if (tid < NN) s_wv[tid] = g_wv[n * NN + tid];
    __syncthreads();
    float lmin = 1e30f, lmax = -1e30f;
    for (int k = tid; k < HW; k += 1024) {
        double a = 0.0;
#pragma unroll
        for (int m = 0; m < NN; m++) {
            float pm = g_cm[(size_t)(n * NN + m) * HW + k] * s_wv[m];
            a += (double)pm;
        }
        float raw = (float)a;
        key[k] = raw;
        lmin = fminf(lmin, raw); lmax = fmaxf(lmax, raw);
    }
    red[tid] = lmin; __syncthreads();
    for (int s = 512; s > 0; s >>= 1) { if (tid < s) red[tid] = fminf(red[tid], red[tid + s]); __syncthreads(); }
    float mn = red[0]; __syncthreads();
    red[tid] = lmax; __syncthreads();
    for (int s = 512; s > 0; s >>= 1) { if (tid < s) red[tid] = fmaxf(red[tid], red[tid + s]); __syncthreads(); }
    float mx = red[0]; __syncthreads();
    float den = (mx - mn) + 1e-12f;
    for (int k = tid; k < HW; k += 1024) {
        float v = (key[k] - mn) / den;
        key[k] = v;
        g_CSA[n * HW + k] = v;
        idv[k] = k;
    }
    for (int e = HW + tid; e < 2048; e += 1024) { key[e] = -1e30f; idv[e] = e; }
    __syncthreads();
    for (int k = 2; k <= 2048; k <<= 1) {
        for (int j = k >> 1; j > 0; j >>= 1) {
            for (int e = tid; e < 2048; e += 1024) {
                int ix = e ^ j;
                if (ix > e) {
                    float ka = key[e], kb = key[ix];
                    int ia = idv[e], ib = idv[ix];
                    bool up = ((e & k) == 0);
                    bool b_before_a = (kb > ka) || (kb == ka && ib < ia);
                    bool dosw = up ? b_before_a : !b_before_a;
                    if (dosw) { key[e] = kb; key[ix] = ka; idv[e] = ib; idv[ix] = ia; }
                }
            }
            __syncthreads();
        }
    }
    for (int e = tid; e < HW; e += 1024) g_idx[n * HW + e] = idv[e];
}

// ---------------- 9: gather + bf16 split ----------------
__global__ void k_gather_split() {
    int b = blockIdx.x;
    int n = b >> 9;
    for (int i = threadIdx.x; i < HW; i += 256) {
        float v = g_NF[(size_t)b * HW + g_idx[n * HW + i]];
        __nv_bfloat16 h = __float2bfloat16(v);
        __nv_bfloat16 l = __float2bfloat16(v - __bfloat162float(h));
        g_Ag_hi[(size_t)b * HW + i] = h;
        g_Ag_lo[(size_t)b * HW + i] = l;
    }
}

// ---------------- 10: weight concat + split (w1/ws and w2 in one launch) ---------
__global__ void k_wsplit(const float* __restrict__ w1, const float* __restrict__ ws,
                         const float* __restrict__ w2) {
    int q = blockIdx.x * 256 + threadIdx.x;
    if (q < MROWS * HW) {
        int i = q % HW, r = q / HW;
        float f;
        if (r < OC * 9) {
            int o = r / 9, t = r % 9;
            f = w1[(o * HW + i) * 9 + t];
        } else {
            f = ws[(r - OC * 9) * HW + i];
        }
        __nv_bfloat16 h = __float2bfloat16(f);
        __nv_bfloat16 l = __float2bfloat16(f - __bfloat162float(h));
        g_Wc_hi[q] = h;
        g_Wc_lo[q] = l;
    } else {
        int q2 = q - MROWS * HW;
        if (q2 >= OC * K2) return;
        int k = q2 % K2, o = q2 / K2;
        int t = k / OC, c = k % OC;
        float f = w2[(o * OC + c) * 9 + t];
        __nv_bfloat16 h = __float2bfloat16(f);
        __nv_bfloat16 l = __float2bfloat16(f - __bfloat162float(h));
        g_W2k_hi[q2] = h;
        g_W2k_lo[q2] = l;
    }
}

// ---------------- 11: fold GEMM, double-buffered, x4 B-fragments (R14) -----------
#define FBUF 10240
#define FSTAGE (4 * FBUF)

__global__ __launch_bounds__(256) void k_gemm_mma() {
    extern __shared__ __align__(16) char dsm[];
    uint32_t base = smem_u32(dsm);
    int n = blockIdx.z;
    int m0 = blockIdx.x * 128, n0 = blockIdx.y * 128;
    const __nv_bfloat16* Bh = g_Ag_hi + (size_t)n * CC * HW;
    const __nv_bfloat16* Bl = g_Ag_lo + (size_t)n * CC * HW;
    int tid = threadIdx.x, lane = tid & 31, wid = tid >> 5;
    int wm = wid & 3, wn = wid >> 2;

    float c[2][8][4];
#pragma unroll
    for (int i = 0; i < 2; i++)
#pragma unroll
        for (int j = 0; j < 8; j++)
#pragma unroll
            for (int q = 0; q < 4; q++) c[i][j][q] = 0.f;

    int lrow = tid >> 1, lk = (tid & 1) * 16;
    const __nv_bfloat16* pAh = g_Wc_hi + (size_t)(m0 + lrow) * HW + lk;
    const __nv_bfloat16* pAl = g_Wc_lo + (size_t)(m0 + lrow) * HW + lk;
    const __nv_bfloat16* pBh = Bh + (size_t)(n0 + lrow) * HW + lk;
    const __nv_bfloat16* pBl = Bl + (size_t)(n0 + lrow) * HW + lk;
    uint32_t so = (uint32_t)(lrow * LDT + lk) * 2;
    int arow = (lane & 15), akoff = 8 * (lane >> 4);
    int bcol = 8 * ((lane >> 4) & 1) + (lane & 7);
    int bko  = 8 * ((lane >> 3) & 1);

    uint4 r0, r1, r2, r3, r4, r5, r6, r7;
#define FLD(k0) do { \
    r0 = *(const uint4*)(pAh + (k0)); r1 = *(const uint4*)(pAh + (k0) + 8); \
    r2 = *(const uint4*)(pAl + (k0)); r3 = *(const uint4*)(pAl + (k0) + 8); \
    r4 = *(const uint4*)(pBh + (k0)); r5 = *(const uint4*)(pBh + (k0) + 8); \
    r6 = *(const uint4*)(pBl + (k0)); r7 = *(const uint4*)(pBl + (k0) + 8); } while (0)
#define FST(s) do { \
    char* sb_ = dsm + (s) * FSTAGE; \
    *(uint4*)(sb_ + so) = r0;            *(uint4*)(sb_ + so + 16) = r1; \
    *(uint4*)(sb_ + FBUF + so) = r2;     *(uint4*)(sb_ + FBUF + so + 16) = r3; \
    *(uint4*)(sb_ + 2*FBUF + so) = r4;   *(uint4*)(sb_ + 2*FBUF + so + 16) = r5; \
    *(uint4*)(sb_ + 3*FBUF + so) = r6;   *(uint4*)(sb_ + 3*FBUF + so + 16) = r7; } while (0)

    FLD(0);
    FST(0);
    __syncthreads();
    for (int kb = 0; kb < 50; kb++) {
        bool more = (kb + 1 < 50);
        if (more) FLD((kb + 1) * 32);
        uint32_t uAh = base + (kb & 1) * FSTAGE;
        uint32_t uAl = uAh + FBUF, uBh = uAh + 2 * FBUF, uBl = uAh + 3 * FBUF;
#pragma unroll
        for (int kk = 0; kk < 32; kk += 16) {
            uint32_t ah[2][4], al[2][4];
#pragma unroll
            for (int i = 0; i < 2; i++) {
                uint32_t ao = (uint32_t)((32 * wm + 16 * i + arow) * LDT + kk + akoff) * 2;
                ldsm_x4(ah[i][0], ah[i][1], ah[i][2], ah[i][3], uAh + ao);
                ldsm_x4(al[i][0], al[i][1], al[i][2], al[i][3], uAl + ao);
            }
#pragma unroll
            for (int jp = 0; jp < 8; jp += 2) {
                uint32_t bo = (uint32_t)((64 * wn + 8 * jp + bcol) * LDT + kk + bko) * 2;
                uint32_t bh0, bh1, bh2, bh3, bl0, bl1, bl2, bl3;
                ldsm_x4(bh0, bh1, bh2, bh3, uBh + bo);
                ldsm_x4(bl0, bl1, bl2, bl3, uBl + bo);
#pragma unroll
                for (int i = 0; i < 2; i++) {
                    hmma(c[i][jp], ah[i], bh0, bh1);
                    hmma(c[i][jp], ah[i], bl0, bl1);
                    hmma(c[i][jp], al[i], bh0, bh1);
                    hmma(c[i][jp + 1], ah[i], bh2, bh3);
                    hmma(c[i][jp + 1], ah[i], bl2, bl3);
                    hmma(c[i][jp + 1], al[i], bh2, bh3);
                }
            }
        }
        if (more) FST((kb + 1) & 1);
        __syncthreads();
    }
#undef FLD
#undef FST
#pragma unroll
    for (int i = 0; i < 2; i++) {
        int rb = m0 + 32 * wm + 16 * i + (lane >> 2);
#pragma unroll
        for (int half = 0; half < 2; half++) {
            int r = rb + half * 8;
#pragma unroll
            for (int j = 0; j < 8; j++) {
                int col = n0 + 64 * wn + 8 * j + (lane & 3) * 2;
                float v0 = c[i][j][half * 2], v1 = c[i][j][half * 2 + 1];
                size_t off;
                __nv_bfloat16 *dh, *dl;
                if (r < OC * 9) {
                    int o = r / 9, t = r % 9;
                    off = ((size_t)n * OC + o) * K1 + t * CC + col;
                    dh = g_Wk1_hi; dl = g_Wk1_lo;
                } else {
                    int o = r - OC * 9;
                    off = ((size_t)n * OC + o) * CC + col;
                    dh = g_Wsc_hi; dl = g_Wsc_lo;
                }
                *(uint32_t*)(dh + off) = pack_hi2(v0, v1);
                *(uint32_t*)(dl + off) = pack_lo2(v0, v1);
            }
        }
    }
}

// ---------------- 12: Xt = (NF*CSA)^T split ----------------
__global__ void k_xt() {
    __shared__ float sT[32][33];
    int n = blockIdx.z;
    int p0 = blockIdx.x * 32, c0 = blockIdx.y * 32;
    int tid = threadIdx.x;
    int tc = tid >> 5, tp = tid & 31;
#pragma unroll
    for (int r = 0; r < 4; r++) {
        int c = c0 + tc + r * 8;
        sT[tc + r * 8][tp] = g_NF[((size_t)n * CC + c) * HW + p0 + tp] * g_CSA[n * HW + p0 + tp];
    }
    __syncthreads();
#pragma unroll
    for (int r = 0; r < 4; r++) {
        int p = p0 + tc + r * 8;
        float v = sT[tp][tc + r * 8];
        __nv_bfloat16 h = __float2bfloat16(v);
        __nv_bfloat16 l = __float2bfloat16(v - __bfloat162float(h));
        g_Xt_hi[((size_t)n * HW + p) * CC + c0 + tp] = h;
        g_Xt_lo[((size_t)n * HW + p) * CC + c0 + tp] = l;
    }
}

// ---------------- 13: conv via mma.sync bf16x3 (R14 version) ----------
#define CBUF 10240
#define CSTG (4 * CBUF)

__global__ __launch_bounds__(256) void k_conv_mma(int mode, const float* __restrict__ bias,
                                                  const float* __restrict__ bsc,
                                                  float* __restrict__ dout) {
    extern __shared__ __align__(16) char dsm[];
    uint32_t base = smem_u32(dsm);
    int n = blockIdx.z;
    int p0 = blockIdx.x * 128;
    int tid = threadIdx.x, lane = tid & 31, wid = tid >> 5;
    int wm = wid & 3, wn = wid >> 2;

    const __nv_bfloat16 *Ah, *Al, *Bh, *Bl;
    int K, Cin, nslab;
    if (mode == 0) {
        Ah = g_Wk1_hi + (size_t)n * OC * K1; Al = g_Wk1_lo + (size_t)n * OC * K1;
        Bh = g_Xt_hi + (size_t)n * HW * CC;  Bl = g_Xt_lo + (size_t)n * HW * CC;
        K = K1; Cin = CC; nslab = K1 / 32;
    } else {
        Ah = g_W2k_hi; Al = g_W2k_lo;
        Bh = g_H1t_hi + (size_t)n * HW * OC; Bl = g_H1t_lo + (size_t)n * HW * OC;
        K = K2; Cin = OC; nslab = K2 / 32;
    }
    int slabs_per_tap = Cin / 32;

    int lrow = tid >> 1, lk = (tid & 1) * 16;
    int bp = p0 + lrow;
    bool prow = (bp < HW);
    int bpx = bp % IMG, bpy = bp / IMG;
    int arow = (lane & 15), akoff = 8 * (lane >> 4);
    int bcol = 8 * ((lane >> 4) & 1) + (lane & 7);
    int bko  = 8 * ((lane >> 3) & 1);
    uint32_t so = (uint32_t)(lrow * LDT + lk) * 2;

    float c[2][8][4];
#pragma unroll
    for (int i = 0; i < 2; i++)
#pragma unroll
        for (int j = 0; j < 8; j++)
#pragma unroll
            for (int q = 0; q < 4; q++) c[i][j][q] = 0.f;

    uint4 ra0, ra1, ra2, ra3, rb0, rb1, rb2, rb3;
#define CLD(kb) do { \
    int t_ = (kb) / slabs_per_tap, c0_ = ((kb) % slabs_per_tap) * 32; \
    int dy_ = t_ / 3 - 1, dx_ = t_ % 3 - 1, off_ = dy_ * IMG + dx_; \
    bool valid_ = prow && ((unsigned)(bpx + dx_) < (unsigned)IMG) && ((unsigned)(bpy + dy_) < (unsigned)IMG); \
    size_t gA_ = (size_t)lrow * K + (kb) * 32 + lk; \
    ra0 = *(const uint4*)(Ah + gA_); ra1 = *(const uint4*)(Ah + gA_ + 8); \
    ra2 = *(const uint4*)(Al + gA_); ra3 = *(const uint4*)(Al + gA_ + 8); \
    rb0 = make_uint4(0,0,0,0); rb1 = rb0; rb2 = rb0; rb3 = rb0; \
    if (valid_) { \
        size_t gB_ = (size_t)(bp + off_) * Cin + c0_ + lk; \
        rb0 = *(const uint4*)(Bh + gB_); rb1 = *(const uint4*)(Bh + gB_ + 8); \
        rb2 = *(const uint4*)(Bl + gB_); rb3 = *(const uint4*)(Bl + gB_ + 8); \
    } } while (0)
#define CST(s) do { \
    char* sb_ = dsm + (s) * CSTG; \
    *(uint4*)(sb_ + so) = ra0;            *(uint4*)(sb_ + so + 16) = ra1; \
    *(uint4*)(sb_ + CBUF + so) = ra2;     *(uint4*)(sb_ + CBUF + so + 16) = ra3; \
    *(uint4*)(sb_ + 2*CBUF + so) = rb0;   *(uint4*)(sb_ + 2*CBUF + so + 16) = rb1; \
    *(uint4*)(sb_ + 3*CBUF + so) = rb2;   *(uint4*)(sb_ + 3*CBUF + so + 16) = rb3; } while (0)
#define CCOMPUTE(s) do { \
    uint32_t uAh_ = base + (s) * CSTG; \
    uint32_t uAl_ = uAh_ + CBUF, uBh_ = uAh_ + 2*CBUF, uBl_ = uAh_ + 3*CBUF; \
    _Pragma("unroll") \
    for (int kk = 0; kk < 32; kk += 16) { \
        uint32_t ah[2][4], al[2][4]; \
        _Pragma("unroll") \
        for (int i = 0; i < 2; i++) { \
            uint32_t ao = (uint32_t)((32 * wm + 16 * i + arow) * LDT + kk + akoff) * 2; \
            ldsm_x4(ah[i][0], ah[i][1], ah[i][2], ah[i][3], uAh_ + ao); \
            ldsm_x4(al[i][0], al[i][1], al[i][2], al[i][3], uAl_ + ao); \
        } \
        _Pragma("unroll") \
        for (int jp = 0; jp < 8; jp += 2) { \
            uint32_t bo = (uint32_t)((64 * wn + 8 * jp + bcol) * LDT + kk + bko) * 2; \
            uint32_t bh0, bh1, bh2, bh3, bl0, bl1, bl2, bl3; \
            ldsm_x4(bh0, bh1, bh2, bh3, uBh_ + bo); \
            ldsm_x4(bl0, bl1, bl2, bl3, uBl_ + bo); \
            _Pragma("unroll") \
            for (int i = 0; i < 2; i++) { \
                hmma(c[i][jp], ah[i], bh0, bh1); \
                hmma(c[i][jp], ah[i], bl0, bl1); \
                hmma(c[i][jp], al[i], bh0, bh1); \
                hmma(c[i][jp + 1], ah[i], bh2, bh3); \
                hmma(c[i][jp + 1], ah[i], bl2, bl3); \
                hmma(c[i][jp + 1], al[i], bh2, bh3); \
            } \
        } \
    } } while (0)

    CLD(0);
    CST(0);
    __syncthreads();
    for (int kb = 0; kb < nslab; kb++) {
        bool more = (kb + 1 < nslab);
        if (more) CLD(kb + 1);
        CCOMPUTE(kb & 1);
        if (more) CST((kb + 1) & 1);
        __syncthreads();
    }
#pragma unroll
    for (int i = 0; i < 2; i++) {
        int rb = 32 * wm + 16 * i + (lane >> 2);
#pragma unroll
        for (int half = 0; half < 2; half++) {
            int o = rb + half * 8;
            float bo = bias[o];
#pragma unroll
            for (int j = 0; j < 8; j++) {
                int p = p0 + 64 * wn + 8 * j + (lane & 3) * 2;
                if (p >= HW) continue;
                float v0 = c[i][j][half * 2] + bo, v1 = c[i][j][half * 2 + 1] + bo;
                if (mode == 0) {
                    float a = fmaxf(v0, 0.f), b2 = fmaxf(v1, 0.f);
                    __nv_bfloat16 ha = __float2bfloat16(a);
                    __nv_bfloat16 la = __float2bfloat16(a - __bfloat162float(ha));
                    __nv_bfloat16 hb = __float2bfloat16(b2);
                    __nv_bfloat16 lb = __float2bfloat16(b2 - __bfloat162float(hb));
                    size_t b0 = ((size_t)n * HW + p) * OC + o;
                    g_H1t_hi[b0] = ha; g_H1t_lo[b0] = la;
                    g_H1t_hi[b0 + OC] = hb; g_H1t_lo[b0 + OC] = lb;
                } else {
                    float2 sc = *(const float2*)&g_SC[((size_t)n * OC + o) * HW + p];
                    *(float2*)&dout[((size_t)n * OC + o) * HW + p] =
                        make_float2(fmaxf(v0 + sc.x, 0.f), fmaxf(v1 + sc.y, 0.f));
                }
            }
        }
    }
    if (mode != 0) return;

    // ---- phase 2: 1x1 shortcut (K=512) ----
#pragma unroll
    for (int i = 0; i < 2; i++)
#pragma unroll
        for (int j = 0; j < 8; j++)
#pragma unroll
            for (int q = 0; q < 4; q++) c[i][j][q] = 0.f;
    const __nv_bfloat16* Sh = g_Wsc_hi + (size_t)n * OC * CC;
    const __nv_bfloat16* Sl = g_Wsc_lo + (size_t)n * OC * CC;
#define SLD(kb) do { \
    size_t gA_ = (size_t)lrow * CC + (kb) * 32 + lk; \
    ra0 = *(const uint4*)(Sh + gA_); ra1 = *(const uint4*)(Sh + gA_ + 8); \
    ra2 = *(const uint4*)(Sl + gA_); ra3 = *(const uint4*)(Sl + gA_ + 8); \
    rb0 = make_uint4(0,0,0,0); rb1 = rb0; rb2 = rb0; rb3 = rb0; \
    if (prow) { \
        size_t gB_ = (size_t)bp * CC + (kb) * 32 + lk; \
        rb0 = *(const uint4*)(Bh + gB_); rb1 = *(const uint4*)(Bh + gB_ + 8); \
        rb2 = *(const uint4*)(Bl + gB_); rb3 = *(const uint4*)(Bl + gB_ + 8); \
    } } while (0)

    __syncthreads();
    SLD(0);
    CST(0);
    __syncthreads();
    for (int kb = 0; kb < CC / 32; kb++) {
        bool more = (kb + 1 < CC / 32);
        if (more) SLD(kb + 1);
        CCOMPUTE(kb & 1);
        if (more) CST((kb + 1) & 1);
        __syncthreads();
    }
#undef SLD
#undef CLD
#undef CST
#undef CCOMPUTE
#pragma unroll
    for (int i = 0; i < 2; i++) {
        int rb = 32 * wm + 16 * i + (lane >> 2);
#pragma unroll
        for (int half = 0; half < 2; half++) {
            int o = rb + half * 8;
            float bo = bsc[o];
#pragma unroll
            for (int j = 0; j < 8; j++) {
                int p = p0 + 64 * wn + 8 * j + (lane & 3) * 2;
                if (p >= HW) continue;
                *(float2*)&g_SC[((size_t)n * OC + o) * HW + p] =
                    make_float2(c[i][j][half * 2] + bo, c[i][j][half * 2 + 1] + bo);
            }
        }
    }
}

// ---------------- launch ----------------
extern "C" void kernel_launch(void* const* d_in, const int* in_sizes, int n_in,
                              void* d_out, int out_size) {
    const float *feats = nullptr, *sisms = nullptr, *w1 = nullptr, *w2 = nullptr, *ws = nullptr;
    const float *b1 = nullptr, *b2 = nullptr, *bs = nullptr;
    for (int i = 0; i < n_in; i++) {
        int s = in_sizes[i];
        const float* p = (const float*)d_in[i];
        if (s == NN * CC * HW) feats = p;
        else if (s == NN * HW) sisms = p;
        else if (s == OC * HW * 9) w1 = p;
        else if (s == OC * OC * 9) w2 = p;
        else if (s == OC * HW) ws = p;
        else if (s == OC) { if (!b1) b1 = p; else if (!b2) b2 = p; else bs = p; }
    }
    float* out = (float*)d_out;

    static int attr_set = 0;
    if (!attr_set) {
        cudaFuncSetAttribute(k_gemm_mma, cudaFuncAttributeMaxDynamicSharedMemorySize, 2 * FSTAGE);
        cudaFuncSetAttribute(k_conv_mma, cudaFuncAttributeMaxDynamicSharedMemorySize, 2 * CSTG);
        attr_set = 1;
    }

    k_norm<<<dim3(50, NN), 256>>>(feats);
    k_siv_raw<<<NN * CC, 256>>>(sisms);
    k_siv_norm<<<NN, CC>>>();
    k_cm<<<dim3(50, NN), 256>>>();
    k_cm_norm<<<NN * NN, 256>>>();
    k_corr<<<NN * NN * NN, 256>>>();
    k_svsm<<<1, 128>>>();
    k_csasort<<<NN, 1024>>>();
    k_gather_split<<<NN * CC, 256>>>();
    k_wsplit<<<(MROWS * HW + OC * K2 + 255) / 256, 256>>>(w1, ws, w2);
    k_gemm_mma<<<dim3(MROWS / 128, CC / 128, NN), 256, 2 * FSTAGE>>>();
    k_xt<<<dim3(50, CC / 32, NN), 256>>>();
    k_conv_mma<<<dim3(13, 1, NN), 256, 2 * CSTG>>>(0, b1, bs, nullptr);
    k_conv_mma<<<dim3(13, 1, NN), 256, 2 * CSTG>>>(1, b2, nullptr, out);
    (void)out_size; (void)n_in;
}